// round 9
// baseline (speedup 1.0000x reference)
#include <cuda_runtime.h>
#include <math.h>
#include <stdint.h>

// ---------------- problem constants ----------------
#define BATCH 4
#define NPIX  65536      // 256*256
#define LHW   64
#define CLAT  32

// per-batch scratch (floats). Weight tiles transposed [n][kpad], pi-paired:
//   idx(n,k) = n*kpad + (k & ~7) + 2*(k & 3) + ((k >> 2) & 1)
// so fragment pair (k, k+4) is adjacent -> one LDG.64 per B fragment.
#define OFFB0    0       // 128 x 64   (8192 floats, K 40 padded to 64, zero-filled)
#define OFFB1    8192    // 128 x 128  (16384)
#define OFFB2    24576
#define OFFB3    40960
#define OFF_BIAS 57344   // 4 * 128 bias rows (fp32)
#define OFF_W4   57856   // 129*2 normalized W4 + bias row (fp32)
#define WSTRIDE  58368

__device__ __align__(16) float g_wmod[BATCH * WSTRIDE];

__device__ __forceinline__ uint32_t f2tf32(float x) {
    uint32_t u;
    asm("cvt.rna.tf32.f32 %0, %1;" : "=r"(u) : "f"(x));
    return u;
}

// ---------------- kernel A: modulate + normalize + pi-pack ----------------
__global__ void modulate_kernel(
    const float* __restrict__ w0, const float* __restrict__ w1,
    const float* __restrict__ w2, const float* __restrict__ w3,
    const float* __restrict__ w4,
    const float* __restrict__ m0, const float* __restrict__ m1,
    const float* __restrict__ m2, const float* __restrict__ m3,
    const float* __restrict__ m4)
{
    int gw   = (blockIdx.x * blockDim.x + threadIdx.x) >> 5;
    int lane = threadIdx.x & 31;
    if (gw >= BATCH * 514) return;
    int b = gw / 514;
    int r = gw % 514;
    int layer, o;
    if (r < 512) { layer = r >> 7; o = r & 127; }
    else         { layer = 4;      o = r - 512; }

    float* g = g_wmod + (size_t)b * WSTRIDE;

    if (layer < 4) {
        const float* w; const float* m; int fr, off, kpad;
        switch (layer) {
          case 0:  w = w0; m = m0; fr = 35;  off = OFFB0; kpad = 64;  break;
          case 1:  w = w1; m = m1; fr = 128; off = OFFB1; kpad = 128; break;
          case 2:  w = w2; m = m2; fr = 128; off = OFFB2; kpad = 128; break;
          default: w = w3; m = m3; fr = 128; off = OFFB3; kpad = 128; break;
        }
        float ss = 0.f;
        for (int k = lane; k < fr; k += 32) {
            float v = w[k * 128 + o] * m[((size_t)b * fr + k) * 128 + o];
            ss += v * v;
        }
        #pragma unroll
        for (int s = 16; s; s >>= 1) ss += __shfl_xor_sync(0xffffffffu, ss, s);
        float inv = 1.f / fmaxf(sqrtf(ss), 1e-12f);
        for (int k = lane; k < kpad; k += 32) {
            float v = 0.f;
            if (k < fr) v = w[k * 128 + o] * m[((size_t)b * fr + k) * 128 + o] * inv;
            int idx = (k & ~7) + 2 * (k & 3) + ((k >> 2) & 1);
            g[off + o * kpad + idx] = __uint_as_float(f2tf32(v));
        }
        if (lane == 0) g[OFF_BIAS + layer * 128 + o] = w[fr * 128 + o];
    } else {
        float ss = 0.f;
        for (int k = lane; k < 128; k += 32) {
            float v = w4[k * 2 + o] * m4[((size_t)b * 128 + k) * 2 + o];
            ss += v * v;
        }
        #pragma unroll
        for (int s = 16; s; s >>= 1) ss += __shfl_xor_sync(0xffffffffu, ss, s);
        float inv = 1.f / fmaxf(sqrtf(ss), 1e-12f);
        for (int k = lane; k < 128; k += 32)
            g[OFF_W4 + k * 2 + o] = w4[k * 2 + o] * m4[((size_t)b * 128 + k) * 2 + o] * inv;
        if (lane == 0) g[OFF_W4 + 256 + o] = w4[128 * 2 + o];
    }
}

// ---------------- kernel B: tf32 mma.sync MLP, B from L2, A double-buffered ----------------
// CTA = 64 pixels, 128 threads (4 warps: 2m x 2n, warp tile 32x32, two n-halves/layer).
#define AP 132           // padded A row stride (floats)
#define BIAS_F   16      // float idx (byte 64): bias 512 + W4 258 = 770 floats
#define W4_F     528
#define A0_B     4096    // 64*132*4 = 33792
#define A1_B     37888
#define SMEM_BYTES 71680

// one n-half MMA pass; B fragments straight from global (L1/L2-cached).
// wt pre-offset to (nb + lr) row, uint2 element (2*lc).
template<int KSTEPS, int KP>
__device__ __forceinline__ void mma_half_g(
    const uint32_t* __restrict__ Asm, const uint2* __restrict__ wt,
    int mbase, int lr, int lc, float (*acc)[4][4])
{
    #pragma unroll
    for (int ks = 0; ks < KSTEPS; ks++) {
        const int kb = ks * 8;
        uint32_t a[2][4];
        #pragma unroll
        for (int mt = 0; mt < 2; mt++) {
            int r0 = (mbase + mt * 16 + lr) * AP + kb + lc;
            a[mt][0] = Asm[r0];
            a[mt][1] = Asm[r0 + 8 * AP];
            a[mt][2] = Asm[r0 + 4];
            a[mt][3] = Asm[r0 + 8 * AP + 4];
        }
        #pragma unroll
        for (int q = 0; q < 4; q++) {
            uint2 bv = wt[q * 8 * (KP / 2) + ks * 4];
            #pragma unroll
            for (int mt = 0; mt < 2; mt++) {
                asm volatile(
                    "mma.sync.aligned.m16n8k8.row.col.f32.tf32.tf32.f32 "
                    "{%0,%1,%2,%3}, {%4,%5,%6,%7}, {%8,%9}, {%0,%1,%2,%3};"
                    : "+f"(acc[mt][q][0]), "+f"(acc[mt][q][1]),
                      "+f"(acc[mt][q][2]), "+f"(acc[mt][q][3])
                    : "r"(a[mt][0]), "r"(a[mt][1]), "r"(a[mt][2]), "r"(a[mt][3]),
                      "r"(bv.x), "r"(bv.y));
            }
        }
    }
}

__global__ __launch_bounds__(128, 3)
void hyponet_kernel(const float* __restrict__ coord,
                    const float* __restrict__ lat,
                    float* __restrict__ out)
{
    extern __shared__ __align__(1024) char smem[];
    float*    smf = (float*)smem;
    uint32_t* Au0 = (uint32_t*)(smem + A0_B);
    uint32_t* Au1 = (uint32_t*)(smem + A1_B);

    const int tid  = threadIdx.x;
    const int warp = tid >> 5, lane = tid & 31;
    const int lr = lane >> 2, lc = lane & 3;
    const int mbase  = (warp & 1) * 32;
    const int nbaseW = (warp >> 1) * 32;
    const int b     = blockIdx.x >> 10;           // 1024 CTAs per batch
    const int pbase = (blockIdx.x & 1023) << 6;   // *64
    const float* gw = g_wmod + (size_t)b * WSTRIDE;

    // ---- prologue: bilinear latent + coord -> A buf0 ----
    if (tid < 64) {
        int p = tid, n = pbase + p;
        int y = n >> 8, x = n & 255;
        const float* c = coord + ((size_t)b * NPIX + n) * 3;
        float sy = (y + 0.5f) * 0.25f - 0.5f;
        float sx = (x + 0.5f) * 0.25f - 0.5f;
        float fy0 = floorf(sy), fx0 = floorf(sx);
        float fy = sy - fy0,    fx = sx - fx0;
        int y0 = max(0, min(LHW - 1, (int)fy0));
        int y1 = max(0, min(LHW - 1, (int)fy0 + 1));
        int x0 = max(0, min(LHW - 1, (int)fx0));
        int x1 = max(0, min(LHW - 1, (int)fx0 + 1));
        float w00 = (1.f - fy) * (1.f - fx), w01 = (1.f - fy) * fx;
        float w10 = fy * (1.f - fx),         w11 = fy * fx;
        const float* base = lat + (size_t)b * LHW * LHW * CLAT;
        const float4* q00 = (const float4*)(base + (y0 * LHW + x0) * CLAT);
        const float4* q01 = (const float4*)(base + (y0 * LHW + x1) * CLAT);
        const float4* q10 = (const float4*)(base + (y1 * LHW + x0) * CLAT);
        const float4* q11 = (const float4*)(base + (y1 * LHW + x1) * CLAT);
        uint32_t* arow = Au0 + p * AP;
        #pragma unroll
        for (int k = 0; k < 8; k++) {
            float4 a = q00[k], bb = q01[k], cc = q10[k], dd = q11[k];
            arow[4 * k + 0] = f2tf32(w00 * a.x + w01 * bb.x + w10 * cc.x + w11 * dd.x);
            arow[4 * k + 1] = f2tf32(w00 * a.y + w01 * bb.y + w10 * cc.y + w11 * dd.y);
            arow[4 * k + 2] = f2tf32(w00 * a.z + w01 * bb.z + w10 * cc.z + w11 * dd.z);
            arow[4 * k + 3] = f2tf32(w00 * a.w + w01 * bb.w + w10 * cc.w + w11 * dd.w);
        }
        arow[32] = f2tf32(c[0]);
        arow[33] = f2tf32(c[1]);
        arow[34] = f2tf32(c[2]);
        #pragma unroll
        for (int k = 35; k < 64; k++) arow[k] = 0;
    } else {
        for (int i = tid - 64; i < 770; i += 64) smf[BIAS_F + i] = gw[OFF_BIAS + i];
    }
    __syncthreads();

    // ---- 4 layers: MMA(buf[L&1]) -> sin -> buf[~L&1]; ONE sync per layer ----
    #define LAYER_PASS(L, KS, KPV, WOFF) do { \
        const uint32_t* Ac = ((L) & 1) ? Au1 : Au0; \
        uint32_t*       An = ((L) & 1) ? Au0 : Au1; \
        const float* biasL = smf + BIAS_F + (L) * 128; \
        _Pragma("unroll") \
        for (int h = 0; h < 2; h++) { \
            const int nb = h * 64 + nbaseW; \
            float acc[2][4][4]; \
            _Pragma("unroll") \
            for (int q = 0; q < 4; q++) { \
                float2 bv = *(const float2*)(biasL + nb + q * 8 + 2 * lc); \
                acc[0][q][0] = bv.x; acc[0][q][1] = bv.y; \
                acc[0][q][2] = bv.x; acc[0][q][3] = bv.y; \
                acc[1][q][0] = bv.x; acc[1][q][1] = bv.y; \
                acc[1][q][2] = bv.x; acc[1][q][3] = bv.y; \
            } \
            const uint2* wt = (const uint2*)(gw + (WOFF)) \
                              + (size_t)(nb + lr) * ((KPV) / 2) + lc; \
            mma_half_g<KS, KPV>(Ac, wt, mbase, lr, lc, acc); \
            _Pragma("unroll") \
            for (int mt = 0; mt < 2; mt++) { \
                _Pragma("unroll") \
                for (int q = 0; q < 4; q++) { \
                    int n0 = nb + q * 8 + 2 * lc; \
                    int r0 = mbase + mt * 16 + lr; \
                    uint2 v01, v23; \
                    v01.x = f2tf32(__sinf(acc[mt][q][0])); \
                    v01.y = f2tf32(__sinf(acc[mt][q][1])); \
                    v23.x = f2tf32(__sinf(acc[mt][q][2])); \
                    v23.y = f2tf32(__sinf(acc[mt][q][3])); \
                    *(uint2*)&An[r0 * AP + n0]       = v01; \
                    *(uint2*)&An[(r0 + 8) * AP + n0] = v23; \
                } \
            } \
        } \
        __syncthreads(); \
    } while (0)

    LAYER_PASS(0, 8, 64, OFFB0);
    LAYER_PASS(1, 16, 128, OFFB1);
    LAYER_PASS(2, 16, 128, OFFB2);
    LAYER_PASS(3, 16, 128, OFFB3);
    #undef LAYER_PASS

    // ---- final: 128 -> 2 dot + 0.5 (fp32), activations in buf0 ----
    {
        const float* w4 = smf + W4_F;
        const float* Af = (const float*)(smem + A0_B);
        int o = tid >> 6, p = tid & 63;
        float acc = w4[256 + o];
        const float* arow = Af + p * AP;
        #pragma unroll 8
        for (int k = 0; k < 128; k += 4) {
            float4 a = *(const float4*)(arow + k);
            acc += a.x * w4[(k + 0) * 2 + o];
            acc += a.y * w4[(k + 1) * 2 + o];
            acc += a.z * w4[(k + 2) * 2 + o];
            acc += a.w * w4[(k + 3) * 2 + o];
        }
        out[((size_t)b * NPIX + pbase + p) * 2 + o] = acc + 0.5f;
    }
}

// ---------------- launch ----------------
extern "C" void kernel_launch(void* const* d_in, const int* in_sizes, int n_in,
                              void* d_out, int out_size)
{
    const float* coord = (const float*)d_in[0];
    const float* lat   = (const float*)d_in[1];

    modulate_kernel<<<(2056 * 32 + 255) / 256, 256>>>(
        (const float*)d_in[2], (const float*)d_in[3], (const float*)d_in[4],
        (const float*)d_in[5], (const float*)d_in[6],
        (const float*)d_in[7], (const float*)d_in[8], (const float*)d_in[9],
        (const float*)d_in[10], (const float*)d_in[11]);

    cudaFuncSetAttribute(hyponet_kernel,
                         cudaFuncAttributeMaxDynamicSharedMemorySize, SMEM_BYTES);
    hyponet_kernel<<<BATCH * (NPIX / 64), 128, SMEM_BYTES>>>(coord, lat, (float*)d_out);
}

// round 11
// speedup vs baseline: 1.6759x; 1.6759x over previous
#include <cuda_runtime.h>
#include <cuda_fp16.h>
#include <math.h>
#include <stdint.h>

// ---------------- problem constants ----------------
#define BATCH 4
#define NPIX  65536      // 256*256
#define LHW   64
#define CLAT  32

// fp16 weight store: per batch, 4 layers x 128 rows(n) x 128 halves(k).
// Within a row: k-blocks of 16, block b stored at position (b ^ (n&7)),
// within-block order pos16: [k0,k0+1,k0+8,k0+9, k2,k3,k10,k11, ...] so each
// m16n8k16 fragment is ONE 8-byte load.
__device__ __align__(16) __half g_wh[BATCH * 4 * 128 * 128];
// fp32 small params: per batch 1024 floats: bias[4][128] @0, W4 perm [128][2] @512, w4bias[2] @768
__device__ __align__(16) float  g_wf[BATCH * 1024];

__device__ __forceinline__ int pos16(int j) {   // j in 0..15
    return (j & 1) | (((j >> 3) & 1) << 1) | (((j >> 1) & 3) << 2);
}

// ================= PTX helpers =================
#define MBARRIER_INIT(mb, cnt) \
    asm volatile("mbarrier.init.shared.b64 [%0], %1;" :: "r"((uint32_t)(mb)), "r"((uint32_t)(cnt)) : "memory")
#define MBARRIER_ARRIVE(mb) \
    asm volatile("mbarrier.arrive.shared.b64 _, [%0];" :: "r"((uint32_t)(mb)) : "memory")
#define MBARRIER_EXPECT_TX(mb, bytes) \
    asm volatile("mbarrier.arrive.expect_tx.shared.b64 _, [%0], %1;" \
                 :: "r"((uint32_t)(mb)), "r"((uint32_t)(bytes)) : "memory")
#define MBARRIER_WAIT_PARITY(mb, par) do { \
    uint32_t _mb = (uint32_t)(mb), _p = (uint32_t)(par), _done; \
    asm volatile("{\n\t.reg .pred p;\n\t" \
        "mbarrier.try_wait.parity.acquire.cta.shared::cta.b64 p, [%1], %2;\n\t" \
        "selp.b32 %0, 1, 0, p;\n\t}" : "=r"(_done) : "r"(_mb), "r"(_p) : "memory"); \
    if (!_done) { \
        asm volatile("{\n\t.reg .pred P1;\n\t" \
            "WL_%=:\n\t" \
            "mbarrier.try_wait.parity.acquire.cta.shared::cta.b64 P1, [%0], %1, 0x989680;\n\t" \
            "@P1 bra.uni WD_%=;\n\t" \
            "bra.uni WL_%=;\n\t" \
            "WD_%=:\n\t}" :: "r"(_mb), "r"(_p) : "memory"); \
    } \
} while (0)
#define BULK_G2S(dst, src, bytes, mb) \
    asm volatile("cp.async.bulk.shared::cluster.global.mbarrier::complete_tx::bytes [%0], [%1], %2, [%3];" \
                 :: "r"((uint32_t)(dst)), "l"(src), "r"((uint32_t)(bytes)), "r"((uint32_t)(mb)) : "memory")

__device__ __forceinline__ uint32_t smem_to_u32(const void* p) {
    uint32_t a;
    asm("{ .reg .u64 t; cvta.to.shared.u64 t, %1; cvt.u32.u64 %0, t; }" : "=r"(a) : "l"(p));
    return a;
}

// ---------------- kernel A: modulate + normalize + fp16 swizzle-pack ----------------
__global__ void modulate_kernel(
    const float* __restrict__ w0, const float* __restrict__ w1,
    const float* __restrict__ w2, const float* __restrict__ w3,
    const float* __restrict__ w4,
    const float* __restrict__ m0, const float* __restrict__ m1,
    const float* __restrict__ m2, const float* __restrict__ m3,
    const float* __restrict__ m4)
{
    int gw   = (blockIdx.x * blockDim.x + threadIdx.x) >> 5;
    int lane = threadIdx.x & 31;
    if (gw >= BATCH * 514) return;
    int b = gw / 514;
    int r = gw % 514;
    int layer, o;
    if (r < 512) { layer = r >> 7; o = r & 127; }
    else         { layer = 4;      o = r - 512; }

    if (layer < 4) {
        const float* w; const float* m; int fr;
        switch (layer) {
          case 0:  w = w0; m = m0; fr = 35;  break;
          case 1:  w = w1; m = m1; fr = 128; break;
          case 2:  w = w2; m = m2; fr = 128; break;
          default: w = w3; m = m3; fr = 128; break;
        }
        float ss = 0.f;
        for (int k = lane; k < fr; k += 32) {
            float v = w[k * 128 + o] * m[((size_t)b * fr + k) * 128 + o];
            ss += v * v;
        }
        #pragma unroll
        for (int s = 16; s; s >>= 1) ss += __shfl_xor_sync(0xffffffffu, ss, s);
        float inv = 1.f / fmaxf(sqrtf(ss), 1e-12f);
        __half* dst = g_wh + ((size_t)(b * 4 + layer) * 128 + o) * 128;
        int sx = o & 7;
        for (int k = lane; k < 128; k += 32) {
            float v = (k < fr) ? w[k * 128 + o] * m[((size_t)b * fr + k) * 128 + o] * inv : 0.f;
            int sidx = (((k >> 4) ^ sx) << 4) + pos16(k & 15);
            dst[sidx] = __float2half_rn(v);
        }
        if (lane == 0) g_wf[b * 1024 + layer * 128 + o] = w[fr * 128 + o];  // bias
    } else {
        float ss = 0.f;
        for (int k = lane; k < 128; k += 32) {
            float v = w4[k * 2 + o] * m4[((size_t)b * 128 + k) * 2 + o];
            ss += v * v;
        }
        #pragma unroll
        for (int s = 16; s; s >>= 1) ss += __shfl_xor_sync(0xffffffffu, ss, s);
        float inv = 1.f / fmaxf(sqrtf(ss), 1e-12f);
        for (int k = lane; k < 128; k += 32) {
            int sidx = (k & ~15) + pos16(k & 15);   // same in-block perm, no row XOR
            g_wf[b * 1024 + 512 + sidx * 2 + o] =
                w4[k * 2 + o] * m4[((size_t)b * 128 + k) * 2 + o] * inv;
        }
        if (lane == 0) g_wf[b * 1024 + 768 + o] = w4[128 * 2 + o];
    }
}

// ---------------- kernel B: fp16 m16n8k16 MLP, 64 px / 128 thr / 2 CTAs-per-SM ----------------
#define SM_WF0    0
#define SM_WF1    8
#define SM_WREL0  16
#define SM_WREL1  24
#define SMF_BIAS  16      // float idx (byte 64): bias 512 + W4 258 = 770 floats
#define SMF_W4    528
#define A0_B      4096    // 64 rows x 256 B = 16384
#define A1_B      20480
#define WB0_B     36864   // 32 KB
#define WB1_B     69632   // 32 KB
#define SMEM_BYTES 102400

// one layer MMA: warp tile 32(m) x 64(n); A rows 256B apart, blocks XOR-swizzled by lr.
template<int KS>
__device__ __forceinline__ void mma_pass(
    const char* __restrict__ Ab, const char* __restrict__ Wb,
    int mbase, int nb, int lr, int lc, float acc[2][8][4])
{
    const char* ab = Ab + (mbase + lr) * 256 + lc * 8;
    const char* wb = Wb + (nb + lr) * 256 + lc * 8;
    #pragma unroll
    for (int ks = 0; ks < KS; ks++) {
        const int so = (ks ^ lr) << 5;
        uint2 a0 = *(const uint2*)(ab + so);           // row r   : {a0, a2}
        uint2 a1 = *(const uint2*)(ab + so + 2048);    // row r+8 : {a1, a3}
        uint2 a2 = *(const uint2*)(ab + so + 4096);    // mt=1
        uint2 a3 = *(const uint2*)(ab + so + 6144);
        #pragma unroll
        for (int q = 0; q < 8; q++) {
            uint2 bv = *(const uint2*)(wb + q * 2048 + so);
            asm volatile(
                "mma.sync.aligned.m16n8k16.row.col.f32.f16.f16.f32 "
                "{%0,%1,%2,%3}, {%4,%5,%6,%7}, {%8,%9}, {%0,%1,%2,%3};"
                : "+f"(acc[0][q][0]), "+f"(acc[0][q][1]),
                  "+f"(acc[0][q][2]), "+f"(acc[0][q][3])
                : "r"(a0.x), "r"(a1.x), "r"(a0.y), "r"(a1.y),
                  "r"(bv.x), "r"(bv.y));
            asm volatile(
                "mma.sync.aligned.m16n8k16.row.col.f32.f16.f16.f32 "
                "{%0,%1,%2,%3}, {%4,%5,%6,%7}, {%8,%9}, {%0,%1,%2,%3};"
                : "+f"(acc[1][q][0]), "+f"(acc[1][q][1]),
                  "+f"(acc[1][q][2]), "+f"(acc[1][q][3])
                : "r"(a2.x), "r"(a3.x), "r"(a2.y), "r"(a3.y),
                  "r"(bv.x), "r"(bv.y));
        }
    }
}

__global__ __launch_bounds__(128)
void hyponet_kernel(const float* __restrict__ coord,
                    const float* __restrict__ lat,
                    float* __restrict__ out)
{
    extern __shared__ __align__(1024) char smem[];
    float* smf = (float*)smem;
    char*  A0  = smem + A0_B;
    char*  A1  = smem + A1_B;
    const uint32_t sb    = smem_to_u32(smem);
    const uint32_t wf0   = sb + SM_WF0,   wf1   = sb + SM_WF1;
    const uint32_t wrel0 = sb + SM_WREL0, wrel1 = sb + SM_WREL1;

    const int tid  = threadIdx.x;
    const int warp = tid >> 5, lane = tid & 31;
    const int lr = lane >> 2, lc = lane & 3;
    const int mbase = (warp & 1) * 32;
    const int nb    = (warp >> 1) * 64;
    const int b     = blockIdx.x >> 10;           // 1024 CTAs per batch
    const int pbase = (blockIdx.x & 1023) << 6;   // *64
    const __half* gwh = g_wh + (size_t)b * 4 * 128 * 128;
    const float*  gwf = g_wf + (size_t)b * 1024;

    if (tid == 0) {
        MBARRIER_INIT(wf0, 1);
        MBARRIER_INIT(wf1, 1);
        MBARRIER_INIT(wrel0, 4);
        MBARRIER_INIT(wrel1, 4);
    }
    __syncthreads();
    if (tid == 0) {
        MBARRIER_EXPECT_TX(wf0, 32768);
        BULK_G2S(sb + WB0_B, gwh + 0 * 16384, 32768, wf0);
        MBARRIER_EXPECT_TX(wf1, 32768);
        BULK_G2S(sb + WB1_B, gwh + 1 * 16384, 32768, wf1);
    }

    // ---- prologue: bilinear latent(32) + coord(3) -> A0 (fp16, swizzled+perm) ----
    if (tid < 64) {
        int p = tid, n = pbase + p;
        int y = n >> 8, x = n & 255;
        const float* c = coord + ((size_t)b * NPIX + n) * 3;
        float va[48];
        #pragma unroll
        for (int k = 35; k < 48; k++) va[k] = 0.f;
        va[32] = c[0]; va[33] = c[1]; va[34] = c[2];
        float sy = (y + 0.5f) * 0.25f - 0.5f;
        float sx = (x + 0.5f) * 0.25f - 0.5f;
        float fy0 = floorf(sy), fx0 = floorf(sx);
        float fy = sy - fy0,    fx = sx - fx0;
        int y0 = max(0, min(LHW - 1, (int)fy0));
        int y1 = max(0, min(LHW - 1, (int)fy0 + 1));
        int x0 = max(0, min(LHW - 1, (int)fx0));
        int x1 = max(0, min(LHW - 1, (int)fx0 + 1));
        float w00 = (1.f - fy) * (1.f - fx), w01 = (1.f - fy) * fx;
        float w10 = fy * (1.f - fx),         w11 = fy * fx;
        const float* base = lat + (size_t)b * LHW * LHW * CLAT;
        const float4* q00 = (const float4*)(base + (y0 * LHW + x0) * CLAT);
        const float4* q01 = (const float4*)(base + (y0 * LHW + x1) * CLAT);
        const float4* q10 = (const float4*)(base + (y1 * LHW + x0) * CLAT);
        const float4* q11 = (const float4*)(base + (y1 * LHW + x1) * CLAT);
        #pragma unroll
        for (int k = 0; k < 8; k++) {
            float4 a = q00[k], bb = q01[k], cc = q10[k], dd = q11[k];
            va[4 * k + 0] = w00 * a.x + w01 * bb.x + w10 * cc.x + w11 * dd.x;
            va[4 * k + 1] = w00 * a.y + w01 * bb.y + w10 * cc.y + w11 * dd.y;
            va[4 * k + 2] = w00 * a.z + w01 * bb.z + w10 * cc.z + w11 * dd.z;
            va[4 * k + 3] = w00 * a.w + w01 * bb.w + w10 * cc.w + w11 * dd.w;
        }
        char* arow = A0 + p * 256;
        int sx2 = p & 7;
        #pragma unroll
        for (int blk = 0; blk < 8; blk++) {
            __half hb[16];
            if (blk < 3) {
                #pragma unroll
                for (int j = 0; j < 16; j++)
                    hb[pos16(j)] = __float2half_rn(va[blk * 16 + j]);
            } else {
                #pragma unroll
                for (int j = 0; j < 16; j++) hb[j] = __float2half_rn(0.f);
            }
            char* dst = arow + ((blk ^ sx2) << 5);
            *(uint4*)dst        = *(const uint4*)hb;
            *(uint4*)(dst + 16) = *(const uint4*)(hb + 8);
        }
    } else {
        for (int i = tid - 64; i < 770; i += 64) smf[SMF_BIAS + i] = gwf[i];
    }
    __syncthreads();

    // ---- 4 layers ----
    #define LAYER_PASS(L, KS, WB_B, WF, WREL, PAR, NEXT_L) do { \
        const char* Ac = ((L) & 1) ? A1 : A0; \
        char*       An = ((L) & 1) ? A0 : A1; \
        const float* biasL = smf + SMF_BIAS + (L) * 128; \
        float acc[2][8][4]; \
        _Pragma("unroll") \
        for (int q = 0; q < 8; q++) { \
            float2 bv = *(const float2*)(biasL + nb + q * 8 + 2 * lc); \
            acc[0][q][0] = bv.x; acc[0][q][1] = bv.y; \
            acc[0][q][2] = bv.x; acc[0][q][3] = bv.y; \
            acc[1][q][0] = bv.x; acc[1][q][1] = bv.y; \
            acc[1][q][2] = bv.x; acc[1][q][3] = bv.y; \
        } \
        MBARRIER_WAIT_PARITY(WF, (PAR)); \
        mma_pass<KS>(Ac, smem + (WB_B), mbase, nb, lr, lc, acc); \
        if (lane == 0) MBARRIER_ARRIVE(WREL); \
        if (tid == 0 && (NEXT_L) >= 0) { \
            MBARRIER_WAIT_PARITY(WREL, (PAR)); \
            MBARRIER_EXPECT_TX(WF, 32768); \
            BULK_G2S(sb + (WB_B), gwh + (NEXT_L) * 16384, 32768, WF); \
        } \
        _Pragma("unroll") \
        for (int mt = 0; mt < 2; mt++) { \
            _Pragma("unroll") \
            for (int q = 0; q < 8; q++) { \
                int n0 = nb + q * 8 + 2 * lc; \
                int r0 = mbase + mt * 16 + lr; \
                int bp = ((n0 >> 4) ^ lr) << 5; \
                int po = (2 * (q & 1) + 4 * lc) * 2; \
                __half2 v01 = __floats2half2_rn(__sinf(acc[mt][q][0]), __sinf(acc[mt][q][1])); \
                __half2 v23 = __floats2half2_rn(__sinf(acc[mt][q][2]), __sinf(acc[mt][q][3])); \
                *(__half2*)(An + r0 * 256 + bp + po)        = v01; \
                *(__half2*)(An + (r0 + 8) * 256 + bp + po)  = v23; \
            } \
        } \
        __syncthreads(); \
    } while (0)

    LAYER_PASS(0, 3, WB0_B, wf0, wrel0, 0, 2);
    LAYER_PASS(1, 8, WB1_B, wf1, wrel1, 0, 3);
    LAYER_PASS(2, 8, WB0_B, wf0, wrel0, 1, -1);
    LAYER_PASS(3, 8, WB1_B, wf1, wrel1, 1, -1);
    #undef LAYER_PASS

    // ---- final: 128 -> 2 dot + 0.5 (fp32); activations in A0 (swizzled fp16) ----
    {
        const float* w4 = smf + SMF_W4;
        int o = tid & 1, p = tid >> 1;
        float acc = smf[SMF_W4 + 256 + o];
        const char* arow = A0 + p * 256;
        int sx2 = p & 7;
        #pragma unroll
        for (int bp = 0; bp < 8; bp++) {
            int ob = bp ^ sx2;                       // original k-block at this position
            const __half2* h2 = (const __half2*)(arow + (bp << 5));
            const float* wb4 = w4 + ob * 32 + o;     // (ob*16 + t)*2 + o
            #pragma unroll
            for (int t = 0; t < 8; t++) {
                float2 av = __half22float2(h2[t]);
                acc += av.x * wb4[4 * t];
                acc += av.y * wb4[4 * t + 2];
            }
        }
        out[((size_t)b * NPIX + pbase + p) * 2 + o] = acc + 0.5f;
    }
}

// ---------------- launch ----------------
extern "C" void kernel_launch(void* const* d_in, const int* in_sizes, int n_in,
                              void* d_out, int out_size)
{
    const float* coord = (const float*)d_in[0];
    const float* lat   = (const float*)d_in[1];

    modulate_kernel<<<(2056 * 32 + 255) / 256, 256>>>(
        (const float*)d_in[2], (const float*)d_in[3], (const float*)d_in[4],
        (const float*)d_in[5], (const float*)d_in[6],
        (const float*)d_in[7], (const float*)d_in[8], (const float*)d_in[9],
        (const float*)d_in[10], (const float*)d_in[11]);

    cudaFuncSetAttribute(hyponet_kernel,
                         cudaFuncAttributeMaxDynamicSharedMemorySize, SMEM_BYTES);
    hyponet_kernel<<<BATCH * (NPIX / 64), 128, SMEM_BYTES>>>(coord, lat, (float*)d_out);
}

// round 12
// speedup vs baseline: 3.0039x; 1.7925x over previous
#include <cuda_runtime.h>
#include <cuda_fp16.h>
#include <math.h>
#include <stdint.h>

// ---------------- problem constants ----------------
#define BATCH 4
#define NPIX  65536      // 256*256
#define LHW   64
#define CLAT  32

// fp16 weight store: per batch, 4 layers x 128 rows(n) x 136 halves(k, plain order,
// last 8 = pad). Row stride 272B keeps SMEM loads conflict-free after bulk copy.
__device__ __align__(16) __half g_wh[BATCH * 4 * 128 * 136];
// fp32 small params per batch (1024 floats): bias[4][128] @0, W4[k][2] @512, w4bias[2] @768
__device__ __align__(16) float  g_wf[BATCH * 1024];

// ================= PTX helpers =================
#define MBARRIER_INIT(mb, cnt) \
    asm volatile("mbarrier.init.shared.b64 [%0], %1;" :: "r"((uint32_t)(mb)), "r"((uint32_t)(cnt)) : "memory")
#define MBARRIER_ARRIVE(mb) \
    asm volatile("mbarrier.arrive.shared.b64 _, [%0];" :: "r"((uint32_t)(mb)) : "memory")
#define MBARRIER_EXPECT_TX(mb, bytes) \
    asm volatile("mbarrier.arrive.expect_tx.shared.b64 _, [%0], %1;" \
                 :: "r"((uint32_t)(mb)), "r"((uint32_t)(bytes)) : "memory")
#define MBARRIER_WAIT_PARITY(mb, par) do { \
    uint32_t _mb = (uint32_t)(mb), _p = (uint32_t)(par), _done; \
    asm volatile("{\n\t.reg .pred p;\n\t" \
        "mbarrier.try_wait.parity.acquire.cta.shared::cta.b64 p, [%1], %2;\n\t" \
        "selp.b32 %0, 1, 0, p;\n\t}" : "=r"(_done) : "r"(_mb), "r"(_p) : "memory"); \
    if (!_done) { \
        asm volatile("{\n\t.reg .pred P1;\n\t" \
            "WL_%=:\n\t" \
            "mbarrier.try_wait.parity.acquire.cta.shared::cta.b64 P1, [%0], %1, 0x989680;\n\t" \
            "@P1 bra.uni WD_%=;\n\t" \
            "bra.uni WL_%=;\n\t" \
            "WD_%=:\n\t}" :: "r"(_mb), "r"(_p) : "memory"); \
    } \
} while (0)
#define BULK_G2S(dst, src, bytes, mb) \
    asm volatile("cp.async.bulk.shared::cluster.global.mbarrier::complete_tx::bytes [%0], [%1], %2, [%3];" \
                 :: "r"((uint32_t)(dst)), "l"(src), "r"((uint32_t)(bytes)), "r"((uint32_t)(mb)) : "memory")

__device__ __forceinline__ uint32_t smem_to_u32(const void* p) {
    uint32_t a;
    asm("{ .reg .u64 t; cvta.to.shared.u64 t, %1; cvt.u32.u64 %0, t; }" : "=r"(a) : "l"(p));
    return a;
}

// ---------------- kernel A: modulate + normalize + fp16 pack (plain layout) ----------------
__global__ void modulate_kernel(
    const float* __restrict__ w0, const float* __restrict__ w1,
    const float* __restrict__ w2, const float* __restrict__ w3,
    const float* __restrict__ w4,
    const float* __restrict__ m0, const float* __restrict__ m1,
    const float* __restrict__ m2, const float* __restrict__ m3,
    const float* __restrict__ m4)
{
    int gw   = (blockIdx.x * blockDim.x + threadIdx.x) >> 5;
    int lane = threadIdx.x & 31;
    if (gw >= BATCH * 514) return;
    int b = gw / 514;
    int r = gw % 514;
    int layer, o;
    if (r < 512) { layer = r >> 7; o = r & 127; }
    else         { layer = 4;      o = r - 512; }

    if (layer < 4) {
        const float* w; const float* m; int fr;
        switch (layer) {
          case 0:  w = w0; m = m0; fr = 35;  break;
          case 1:  w = w1; m = m1; fr = 128; break;
          case 2:  w = w2; m = m2; fr = 128; break;
          default: w = w3; m = m3; fr = 128; break;
        }
        float ss = 0.f;
        for (int k = lane; k < fr; k += 32) {
            float v = w[k * 128 + o] * m[((size_t)b * fr + k) * 128 + o];
            ss += v * v;
        }
        #pragma unroll
        for (int s = 16; s; s >>= 1) ss += __shfl_xor_sync(0xffffffffu, ss, s);
        float inv = 1.f / fmaxf(sqrtf(ss), 1e-12f);
        __half* dst = g_wh + (size_t)((b * 4 + layer) * 128 + o) * 136;
        for (int k = lane; k < 136; k += 32) {
            float v = (k < fr) ? w[k * 128 + o] * m[((size_t)b * fr + k) * 128 + o] * inv : 0.f;
            dst[k] = __float2half_rn(v);
        }
        if (lane == 0) g_wf[b * 1024 + layer * 128 + o] = w[fr * 128 + o];  // bias
    } else {
        float ss = 0.f;
        for (int k = lane; k < 128; k += 32) {
            float v = w4[k * 2 + o] * m4[((size_t)b * 128 + k) * 2 + o];
            ss += v * v;
        }
        #pragma unroll
        for (int s = 16; s; s >>= 1) ss += __shfl_xor_sync(0xffffffffu, ss, s);
        float inv = 1.f / fmaxf(sqrtf(ss), 1e-12f);
        for (int k = lane; k < 128; k += 32)
            g_wf[b * 1024 + 512 + k * 2 + o] =
                w4[k * 2 + o] * m4[((size_t)b * 128 + k) * 2 + o] * inv;
        if (lane == 0) g_wf[b * 1024 + 768 + o] = w4[128 * 2 + o];
    }
}

// ---------------- kernel B: fp16 m16n8k16 MLP, 64 px / 128 thr / 3 CTAs-per-SM ----------------
#define ASTR 272          // bytes per A row (136 halves); 272/4 mod 32 = 4 -> conflict-free
#define SM_WF0    0
#define SM_WF1    8
#define SM_WREL0  16
#define SM_WREL1  24
#define SMF_BIAS  16      // float idx (byte 64): bias 512 + W4 256 + 2 = 770 floats
#define SMF_W4    528
#define A0_B      4096    // 64 * 272 = 17408
#define A1_B      21504
#define WB0_B     38912   // 64 rows * 272B = 17408 (n half for warp pair 0)
#define WB1_B     56320
#define SMEM_BYTES 73728

// one layer MMA: warp tile 32(m) x 64(n); scalar LDS.32 fragment loads, plain layout.
// Wb points at this warp-pair's 64-row half buffer (local rows 0..63).
template<int KS>
__device__ __forceinline__ void mma_pass(
    const char* __restrict__ Ab, const char* __restrict__ Wb,
    int mbase, int lr, int lc, float acc[2][8][4])
{
    const char* ab = Ab + (mbase + lr) * ASTR + 4 * lc;
    const char* wb = Wb + lr * ASTR + 4 * lc;
    #pragma unroll
    for (int ks = 0; ks < KS; ks++) {
        const int ko = 32 * ks;
        uint32_t a[2][4];
        #pragma unroll
        for (int mt = 0; mt < 2; mt++) {
            const char* ar = ab + mt * 16 * ASTR + ko;
            a[mt][0] = *(const uint32_t*)ar;                    // (r,   klo)
            a[mt][1] = *(const uint32_t*)(ar + 8 * ASTR);       // (r+8, klo)
            a[mt][2] = *(const uint32_t*)(ar + 16);             // (r,   khi)
            a[mt][3] = *(const uint32_t*)(ar + 8 * ASTR + 16);  // (r+8, khi)
        }
        #pragma unroll
        for (int q = 0; q < 8; q++) {
            const char* wr = wb + q * 8 * ASTR + ko;
            uint32_t b0 = *(const uint32_t*)wr;
            uint32_t b1 = *(const uint32_t*)(wr + 16);
            #pragma unroll
            for (int mt = 0; mt < 2; mt++) {
                asm volatile(
                    "mma.sync.aligned.m16n8k16.row.col.f32.f16.f16.f32 "
                    "{%0,%1,%2,%3}, {%4,%5,%6,%7}, {%8,%9}, {%0,%1,%2,%3};"
                    : "+f"(acc[mt][q][0]), "+f"(acc[mt][q][1]),
                      "+f"(acc[mt][q][2]), "+f"(acc[mt][q][3])
                    : "r"(a[mt][0]), "r"(a[mt][1]), "r"(a[mt][2]), "r"(a[mt][3]),
                      "r"(b0), "r"(b1));
            }
        }
    }
}

__global__ __launch_bounds__(128, 3)
void hyponet_kernel(const float* __restrict__ coord,
                    const float* __restrict__ lat,
                    float* __restrict__ out)
{
    extern __shared__ __align__(1024) char smem[];
    float* smf = (float*)smem;
    char*  A0  = smem + A0_B;
    char*  A1  = smem + A1_B;
    const uint32_t sb = smem_to_u32(smem);

    const int tid  = threadIdx.x;
    const int warp = tid >> 5, lane = tid & 31;
    const int lr = lane >> 2, lc = lane & 3;
    const int mbase = (warp & 1) * 32;
    const int h     = warp >> 1;                  // n-half owned by this warp pair
    const int b     = blockIdx.x >> 10;           // 1024 CTAs per batch
    const int pbase = (blockIdx.x & 1023) << 6;   // *64
    const __half* gwh = g_wh + (size_t)b * 4 * 128 * 136;
    const float*  gwf = g_wf + (size_t)b * 1024;

    const uint32_t wf_m   = sb + (h ? SM_WF1 : SM_WF0);
    const uint32_t wrel_m = sb + (h ? SM_WREL1 : SM_WREL0);
    char* wb_sm = smem + (h ? WB1_B : WB0_B);
    const __half* src_h = gwh + h * 8704;         // half h of layer 0 (halves)

    if (tid == 0) {
        MBARRIER_INIT(sb + SM_WF0, 1);
        MBARRIER_INIT(sb + SM_WF1, 1);
        MBARRIER_INIT(sb + SM_WREL0, 2);
        MBARRIER_INIT(sb + SM_WREL1, 2);
    }
    __syncthreads();
    if (tid == 0) {
        MBARRIER_EXPECT_TX(sb + SM_WF0, 17408);
        BULK_G2S(sb + WB0_B, gwh + 0 * 8704, 17408, sb + SM_WF0);
        MBARRIER_EXPECT_TX(sb + SM_WF1, 17408);
        BULK_G2S(sb + WB1_B, gwh + 1 * 8704, 17408, sb + SM_WF1);
    }

    // ---- prologue: bilinear latent(32) + coord(3) + pad -> A0 rows (plain halves) ----
    if (tid < 64) {
        int p = tid, n = pbase + p;
        int y = n >> 8, x = n & 255;
        const float* c = coord + ((size_t)b * NPIX + n) * 3;
        float va[48];
        #pragma unroll
        for (int k = 35; k < 48; k++) va[k] = 0.f;
        va[32] = c[0]; va[33] = c[1]; va[34] = c[2];
        float sy = (y + 0.5f) * 0.25f - 0.5f;
        float sx = (x + 0.5f) * 0.25f - 0.5f;
        float fy0 = floorf(sy), fx0 = floorf(sx);
        float fy = sy - fy0,    fx = sx - fx0;
        int y0 = max(0, min(LHW - 1, (int)fy0));
        int y1 = max(0, min(LHW - 1, (int)fy0 + 1));
        int x0 = max(0, min(LHW - 1, (int)fx0));
        int x1 = max(0, min(LHW - 1, (int)fx0 + 1));
        float w00 = (1.f - fy) * (1.f - fx), w01 = (1.f - fy) * fx;
        float w10 = fy * (1.f - fx),         w11 = fy * fx;
        const float* base = lat + (size_t)b * LHW * LHW * CLAT;
        const float4* q00 = (const float4*)(base + (y0 * LHW + x0) * CLAT);
        const float4* q01 = (const float4*)(base + (y0 * LHW + x1) * CLAT);
        const float4* q10 = (const float4*)(base + (y1 * LHW + x0) * CLAT);
        const float4* q11 = (const float4*)(base + (y1 * LHW + x1) * CLAT);
        #pragma unroll
        for (int k = 0; k < 8; k++) {
            float4 a = q00[k], bb = q01[k], cc = q10[k], dd = q11[k];
            va[4 * k + 0] = w00 * a.x + w01 * bb.x + w10 * cc.x + w11 * dd.x;
            va[4 * k + 1] = w00 * a.y + w01 * bb.y + w10 * cc.y + w11 * dd.y;
            va[4 * k + 2] = w00 * a.z + w01 * bb.z + w10 * cc.z + w11 * dd.z;
            va[4 * k + 3] = w00 * a.w + w01 * bb.w + w10 * cc.w + w11 * dd.w;
        }
        __half2* arow = (__half2*)(A0 + p * ASTR);
        #pragma unroll
        for (int j = 0; j < 24; j++)
            arow[j] = __floats2half2_rn(va[2 * j], va[2 * j + 1]);
    } else {
        for (int i = tid - 64; i < 770; i += 64) smf[SMF_BIAS + i] = gwf[i];
    }
    __syncthreads();

    // ---- 4 layers: wait weights(own half) -> MMA -> release -> refill -> sin -> other A buf ----
    #define LAYER_PASS(L, KS) do { \
        const char* Ac = ((L) & 1) ? A1 : A0; \
        char*       An = ((L) & 1) ? A0 : A1; \
        const float* biasL = smf + SMF_BIAS + (L) * 128; \
        float acc[2][8][4]; \
        _Pragma("unroll") \
        for (int q = 0; q < 8; q++) { \
            float2 bv = *(const float2*)(biasL + h * 64 + q * 8 + 2 * lc); \
            acc[0][q][0] = bv.x; acc[0][q][1] = bv.y; \
            acc[0][q][2] = bv.x; acc[0][q][3] = bv.y; \
            acc[1][q][0] = bv.x; acc[1][q][1] = bv.y; \
            acc[1][q][2] = bv.x; acc[1][q][3] = bv.y; \
        } \
        MBARRIER_WAIT_PARITY(wf_m, (L) & 1); \
        mma_pass<KS>(Ac, wb_sm, mbase, lr, lc, acc); \
        if (lane == 0) MBARRIER_ARRIVE(wrel_m); \
        if ((warp & 1) == 0 && (L) < 3) { \
            MBARRIER_WAIT_PARITY(wrel_m, (L) & 1); \
            if (lane == 0) { \
                MBARRIER_EXPECT_TX(wf_m, 17408); \
                BULK_G2S(smem_to_u32(wb_sm), src_h + ((L) + 1) * 17408, 17408, wf_m); \
            } \
        } \
        _Pragma("unroll") \
        for (int mt = 0; mt < 2; mt++) { \
            _Pragma("unroll") \
            for (int q = 0; q < 8; q++) { \
                int n0 = h * 64 + q * 8 + 2 * lc; \
                int r0 = mbase + mt * 16 + lr; \
                __half2 v01 = __floats2half2_rn(__sinf(acc[mt][q][0]), __sinf(acc[mt][q][1])); \
                __half2 v23 = __floats2half2_rn(__sinf(acc[mt][q][2]), __sinf(acc[mt][q][3])); \
                *(__half2*)(An + r0 * ASTR + 2 * n0)       = v01; \
                *(__half2*)(An + (r0 + 8) * ASTR + 2 * n0) = v23; \
            } \
        } \
        __syncthreads(); \
    } while (0)

    LAYER_PASS(0, 3);
    LAYER_PASS(1, 8);
    LAYER_PASS(2, 8);
    LAYER_PASS(3, 8);
    #undef LAYER_PASS

    // ---- final: 128 -> 2 dot + 0.5 (fp32); activations in A0 (plain halves) ----
    {
        int o = tid & 1, p = tid >> 1;
        float acc = smf[SMF_W4 + 256 + o];
        const __half2* arow = (const __half2*)(A0 + p * ASTR);
        const float* w4 = smf + SMF_W4 + o;
        #pragma unroll
        for (int j = 0; j < 64; j++) {
            float2 av = __half22float2(arow[j]);
            acc += av.x * w4[4 * j];
            acc += av.y * w4[4 * j + 2];
        }
        out[((size_t)b * NPIX + pbase + p) * 2 + o] = acc + 0.5f;
    }
}

// ---------------- launch ----------------
extern "C" void kernel_launch(void* const* d_in, const int* in_sizes, int n_in,
                              void* d_out, int out_size)
{
    const float* coord = (const float*)d_in[0];
    const float* lat   = (const float*)d_in[1];

    modulate_kernel<<<(2056 * 32 + 255) / 256, 256>>>(
        (const float*)d_in[2], (const float*)d_in[3], (const float*)d_in[4],
        (const float*)d_in[5], (const float*)d_in[6],
        (const float*)d_in[7], (const float*)d_in[8], (const float*)d_in[9],
        (const float*)d_in[10], (const float*)d_in[11]);

    cudaFuncSetAttribute(hyponet_kernel,
                         cudaFuncAttributeMaxDynamicSharedMemorySize, SMEM_BYTES);
    hyponet_kernel<<<BATCH * (NPIX / 64), 128, SMEM_BYTES>>>(coord, lat, (float*)d_out);
}

// round 13
// speedup vs baseline: 3.3420x; 1.1126x over previous
#include <cuda_runtime.h>
#include <cuda_fp16.h>
#include <math.h>
#include <stdint.h>

// ---------------- problem constants ----------------
#define BATCH 4
#define NPIX  65536      // 256*256
#define LHW   64
#define CLAT  32

// fp16 weight store: per batch, 4 layers x 128 rows(n) x 136 halves(k, plain order,
// last 8 = pad). Row stride 272B keeps SMEM loads conflict-free after bulk copy.
__device__ __align__(16) __half g_wh[BATCH * 4 * 128 * 136];
// fp32 small params per batch (1024 floats): bias[4][128] @0, W4[k][2] @512, w4bias[2] @768
__device__ __align__(16) float  g_wf[BATCH * 1024];

// ================= PTX helpers =================
#define MBARRIER_INIT(mb, cnt) \
    asm volatile("mbarrier.init.shared.b64 [%0], %1;" :: "r"((uint32_t)(mb)), "r"((uint32_t)(cnt)) : "memory")
#define MBARRIER_ARRIVE(mb) \
    asm volatile("mbarrier.arrive.shared.b64 _, [%0];" :: "r"((uint32_t)(mb)) : "memory")
#define MBARRIER_EXPECT_TX(mb, bytes) \
    asm volatile("mbarrier.arrive.expect_tx.shared.b64 _, [%0], %1;" \
                 :: "r"((uint32_t)(mb)), "r"((uint32_t)(bytes)) : "memory")
#define MBARRIER_WAIT_PARITY(mb, par) do { \
    uint32_t _mb = (uint32_t)(mb), _p = (uint32_t)(par), _done; \
    asm volatile("{\n\t.reg .pred p;\n\t" \
        "mbarrier.try_wait.parity.acquire.cta.shared::cta.b64 p, [%1], %2;\n\t" \
        "selp.b32 %0, 1, 0, p;\n\t}" : "=r"(_done) : "r"(_mb), "r"(_p) : "memory"); \
    if (!_done) { \
        asm volatile("{\n\t.reg .pred P1;\n\t" \
            "WL_%=:\n\t" \
            "mbarrier.try_wait.parity.acquire.cta.shared::cta.b64 P1, [%0], %1, 0x989680;\n\t" \
            "@P1 bra.uni WD_%=;\n\t" \
            "bra.uni WL_%=;\n\t" \
            "WD_%=:\n\t}" :: "r"(_mb), "r"(_p) : "memory"); \
    } \
} while (0)
#define BULK_G2S(dst, src, bytes, mb) \
    asm volatile("cp.async.bulk.shared::cluster.global.mbarrier::complete_tx::bytes [%0], [%1], %2, [%3];" \
                 :: "r"((uint32_t)(dst)), "l"(src), "r"((uint32_t)(bytes)), "r"((uint32_t)(mb)) : "memory")
#define LDMATRIX_X4(r0, r1, r2, r3, addr) \
    asm volatile("ldmatrix.sync.aligned.m8n8.x4.shared.b16 {%0,%1,%2,%3}, [%4];" \
                 : "=r"(r0), "=r"(r1), "=r"(r2), "=r"(r3) : "r"(addr))

__device__ __forceinline__ uint32_t smem_to_u32(const void* p) {
    uint32_t a;
    asm("{ .reg .u64 t; cvta.to.shared.u64 t, %1; cvt.u32.u64 %0, t; }" : "=r"(a) : "l"(p));
    return a;
}

// ---------------- kernel A: modulate + normalize + fp16 pack (plain layout) ----------------
__global__ void modulate_kernel(
    const float* __restrict__ w0, const float* __restrict__ w1,
    const float* __restrict__ w2, const float* __restrict__ w3,
    const float* __restrict__ w4,
    const float* __restrict__ m0, const float* __restrict__ m1,
    const float* __restrict__ m2, const float* __restrict__ m3,
    const float* __restrict__ m4)
{
    int gw   = (blockIdx.x * blockDim.x + threadIdx.x) >> 5;
    int lane = threadIdx.x & 31;
    if (gw >= BATCH * 514) return;
    int b = gw / 514;
    int r = gw % 514;
    int layer, o;
    if (r < 512) { layer = r >> 7; o = r & 127; }
    else         { layer = 4;      o = r - 512; }

    if (layer < 4) {
        const float* w; const float* m; int fr;
        switch (layer) {
          case 0:  w = w0; m = m0; fr = 35;  break;
          case 1:  w = w1; m = m1; fr = 128; break;
          case 2:  w = w2; m = m2; fr = 128; break;
          default: w = w3; m = m3; fr = 128; break;
        }
        float ss = 0.f;
        for (int k = lane; k < fr; k += 32) {
            float v = w[k * 128 + o] * m[((size_t)b * fr + k) * 128 + o];
            ss += v * v;
        }
        #pragma unroll
        for (int s = 16; s; s >>= 1) ss += __shfl_xor_sync(0xffffffffu, ss, s);
        float inv = 1.f / fmaxf(sqrtf(ss), 1e-12f);
        __half* dst = g_wh + (size_t)((b * 4 + layer) * 128 + o) * 136;
        for (int k = lane; k < 136; k += 32) {
            float v = (k < fr) ? w[k * 128 + o] * m[((size_t)b * fr + k) * 128 + o] * inv : 0.f;
            dst[k] = __float2half_rn(v);
        }
        if (lane == 0) g_wf[b * 1024 + layer * 128 + o] = w[fr * 128 + o];  // bias
    } else {
        float ss = 0.f;
        for (int k = lane; k < 128; k += 32) {
            float v = w4[k * 2 + o] * m4[((size_t)b * 128 + k) * 2 + o];
            ss += v * v;
        }
        #pragma unroll
        for (int s = 16; s; s >>= 1) ss += __shfl_xor_sync(0xffffffffu, ss, s);
        float inv = 1.f / fmaxf(sqrtf(ss), 1e-12f);
        for (int k = lane; k < 128; k += 32)
            g_wf[b * 1024 + 512 + k * 2 + o] =
                w4[k * 2 + o] * m4[((size_t)b * 128 + k) * 2 + o] * inv;
        if (lane == 0) g_wf[b * 1024 + 768 + o] = w4[128 * 2 + o];
    }
}

// ---------------- kernel B: fp16 m16n8k16 MLP, 64 px / 128 thr / 4 CTAs-per-SM ----------------
#define ASTR 272          // bytes per A/W row (136 halves); 272/4 mod 32 = 4 -> conflict-free
#define SM_WF0    0
#define SM_WF1    8
#define SM_WREL0  16
#define SM_WREL1  24
#define SMF_BIAS  16      // float idx (byte 64): bias 512 + W4 256 + 2 = 770 floats
#define SMF_W4    528
#define A0_B      4096    // 64 * 272 = 17408  (single A buffer, updated in place)
#define WB0_B     21504   // 64 rows * 272B = 17408 (n half for warp pair 0)
#define WB1_B     38912
#define SMEM_BYTES 56320

// one layer MMA via ldmatrix.x4; A updated in place (caller bars around epilogue).
// a_base: per-lane ldmatrix base for mt=0,ks=0. w_base: per-lane base for q-pair 0,ks=0.
template<int KS>
__device__ __forceinline__ void mma_pass(uint32_t a_base, uint32_t w_base,
                                         float acc[2][8][4])
{
    #pragma unroll
    for (int ks = 0; ks < KS; ks++) {
        uint32_t a[2][4];
        #pragma unroll
        for (int mt = 0; mt < 2; mt++)
            LDMATRIX_X4(a[mt][0], a[mt][1], a[mt][2], a[mt][3],
                        a_base + mt * 16 * ASTR + 32 * ks);
        #pragma unroll
        for (int qp = 0; qp < 4; qp++) {
            uint32_t b0, b1, b2, b3;
            LDMATRIX_X4(b0, b1, b2, b3, w_base + qp * 16 * ASTR + 32 * ks);
            #pragma unroll
            for (int mt = 0; mt < 2; mt++) {
                asm volatile(
                    "mma.sync.aligned.m16n8k16.row.col.f32.f16.f16.f32 "
                    "{%0,%1,%2,%3}, {%4,%5,%6,%7}, {%8,%9}, {%0,%1,%2,%3};"
                    : "+f"(acc[mt][2 * qp][0]), "+f"(acc[mt][2 * qp][1]),
                      "+f"(acc[mt][2 * qp][2]), "+f"(acc[mt][2 * qp][3])
                    : "r"(a[mt][0]), "r"(a[mt][1]), "r"(a[mt][2]), "r"(a[mt][3]),
                      "r"(b0), "r"(b1));
                asm volatile(
                    "mma.sync.aligned.m16n8k16.row.col.f32.f16.f16.f32 "
                    "{%0,%1,%2,%3}, {%4,%5,%6,%7}, {%8,%9}, {%0,%1,%2,%3};"
                    : "+f"(acc[mt][2 * qp + 1][0]), "+f"(acc[mt][2 * qp + 1][1]),
                      "+f"(acc[mt][2 * qp + 1][2]), "+f"(acc[mt][2 * qp + 1][3])
                    : "r"(a[mt][0]), "r"(a[mt][1]), "r"(a[mt][2]), "r"(a[mt][3]),
                      "r"(b2), "r"(b3));
            }
        }
    }
}

__global__ __launch_bounds__(128, 4)
void hyponet_kernel(const float* __restrict__ coord,
                    const float* __restrict__ lat,
                    float* __restrict__ out)
{
    extern __shared__ __align__(1024) char smem[];
    float* smf = (float*)smem;
    char*  A0  = smem + A0_B;
    const uint32_t sb = smem_to_u32(smem);

    const int tid  = threadIdx.x;
    const int warp = tid >> 5, lane = tid & 31;
    const int lr = lane >> 2, lc = lane & 3;
    const int mbase = (warp & 1) * 32;
    const int h     = warp >> 1;                  // n-half owned by this warp pair
    const int b     = blockIdx.x >> 10;           // 1024 CTAs per batch
    const int pbase = (blockIdx.x & 1023) << 6;   // *64
    const __half* gwh = g_wh + (size_t)b * 4 * 128 * 136;
    const float*  gwf = g_wf + (size_t)b * 1024;

    const uint32_t wf_m   = sb + (h ? SM_WF1 : SM_WF0);
    const uint32_t wrel_m = sb + (h ? SM_WREL1 : SM_WREL0);
    const uint32_t wb_u   = sb + (h ? WB1_B : WB0_B);
    const __half* src_h = gwh + h * 8704;         // half h of layer 0 (halves)

    // per-lane ldmatrix base addresses
    const uint32_t a_base = sb + A0_B + (mbase + (lane & 15)) * ASTR + ((lane >> 4) << 4);
    const uint32_t w_base = wb_u + ((lane & 7) + ((lane >> 4) << 3)) * ASTR
                                 + (((lane >> 3) & 1) << 4);

    if (tid == 0) {
        MBARRIER_INIT(sb + SM_WF0, 1);
        MBARRIER_INIT(sb + SM_WF1, 1);
        MBARRIER_INIT(sb + SM_WREL0, 2);
        MBARRIER_INIT(sb + SM_WREL1, 2);
    }
    __syncthreads();
    if (tid == 0) {
        MBARRIER_EXPECT_TX(sb + SM_WF0, 17408);
        BULK_G2S(sb + WB0_B, gwh + 0 * 8704, 17408, sb + SM_WF0);
        MBARRIER_EXPECT_TX(sb + SM_WF1, 17408);
        BULK_G2S(sb + WB1_B, gwh + 1 * 8704, 17408, sb + SM_WF1);
    }

    // ---- prologue: bilinear latent(32) + coord(3) + pad -> A0 rows (plain halves) ----
    if (tid < 64) {
        int p = tid, n = pbase + p;
        int y = n >> 8, x = n & 255;
        const float* c = coord + ((size_t)b * NPIX + n) * 3;
        float va[48];
        #pragma unroll
        for (int k = 35; k < 48; k++) va[k] = 0.f;
        va[32] = c[0]; va[33] = c[1]; va[34] = c[2];
        float sy = (y + 0.5f) * 0.25f - 0.5f;
        float sx = (x + 0.5f) * 0.25f - 0.5f;
        float fy0 = floorf(sy), fx0 = floorf(sx);
        float fy = sy - fy0,    fx = sx - fx0;
        int y0 = max(0, min(LHW - 1, (int)fy0));
        int y1 = max(0, min(LHW - 1, (int)fy0 + 1));
        int x0 = max(0, min(LHW - 1, (int)fx0));
        int x1 = max(0, min(LHW - 1, (int)fx0 + 1));
        float w00 = (1.f - fy) * (1.f - fx), w01 = (1.f - fy) * fx;
        float w10 = fy * (1.f - fx),         w11 = fy * fx;
        const float* base = lat + (size_t)b * LHW * LHW * CLAT;
        const float4* q00 = (const float4*)(base + (y0 * LHW + x0) * CLAT);
        const float4* q01 = (const float4*)(base + (y0 * LHW + x1) * CLAT);
        const float4* q10 = (const float4*)(base + (y1 * LHW + x0) * CLAT);
        const float4* q11 = (const float4*)(base + (y1 * LHW + x1) * CLAT);
        #pragma unroll
        for (int k = 0; k < 8; k++) {
            float4 a = q00[k], bb = q01[k], cc = q10[k], dd = q11[k];
            va[4 * k + 0] = w00 * a.x + w01 * bb.x + w10 * cc.x + w11 * dd.x;
            va[4 * k + 1] = w00 * a.y + w01 * bb.y + w10 * cc.y + w11 * dd.y;
            va[4 * k + 2] = w00 * a.z + w01 * bb.z + w10 * cc.z + w11 * dd.z;
            va[4 * k + 3] = w00 * a.w + w01 * bb.w + w10 * cc.w + w11 * dd.w;
        }
        __half2* arow = (__half2*)(A0 + p * ASTR);
        #pragma unroll
        for (int j = 0; j < 24; j++)
            arow[j] = __floats2half2_rn(va[2 * j], va[2 * j + 1]);
    } else {
        for (int i = tid - 64; i < 770; i += 64) smf[SMF_BIAS + i] = gwf[i];
    }
    __syncthreads();

    // ---- 4 layers: wait weights -> MMA -> release/refill -> bar -> sin in place -> bar ----
    #define LAYER_PASS(L, KS) do { \
        const float* biasL = smf + SMF_BIAS + (L) * 128; \
        float acc[2][8][4]; \
        _Pragma("unroll") \
        for (int q = 0; q < 8; q++) { \
            float2 bv = *(const float2*)(biasL + h * 64 + q * 8 + 2 * lc); \
            acc[0][q][0] = bv.x; acc[0][q][1] = bv.y; \
            acc[0][q][2] = bv.x; acc[0][q][3] = bv.y; \
            acc[1][q][0] = bv.x; acc[1][q][1] = bv.y; \
            acc[1][q][2] = bv.x; acc[1][q][3] = bv.y; \
        } \
        MBARRIER_WAIT_PARITY(wf_m, (L) & 1); \
        mma_pass<KS>(a_base, w_base, acc); \
        if (lane == 0) MBARRIER_ARRIVE(wrel_m); \
        if ((warp & 1) == 0 && (L) < 3) { \
            MBARRIER_WAIT_PARITY(wrel_m, (L) & 1); \
            if (lane == 0) { \
                MBARRIER_EXPECT_TX(wf_m, 17408); \
                BULK_G2S(wb_u, src_h + ((L) + 1) * 17408, 17408, wf_m); \
            } \
        } \
        __syncthreads(); \
        _Pragma("unroll") \
        for (int mt = 0; mt < 2; mt++) { \
            _Pragma("unroll") \
            for (int q = 0; q < 8; q++) { \
                int n0 = h * 64 + q * 8 + 2 * lc; \
                int r0 = mbase + mt * 16 + lr; \
                __half2 v01 = __floats2half2_rn(__sinf(acc[mt][q][0]), __sinf(acc[mt][q][1])); \
                __half2 v23 = __floats2half2_rn(__sinf(acc[mt][q][2]), __sinf(acc[mt][q][3])); \
                *(__half2*)(A0 + r0 * ASTR + 2 * n0)       = v01; \
                *(__half2*)(A0 + (r0 + 8) * ASTR + 2 * n0) = v23; \
            } \
        } \
        __syncthreads(); \
    } while (0)

    LAYER_PASS(0, 3);
    LAYER_PASS(1, 8);
    LAYER_PASS(2, 8);
    LAYER_PASS(3, 8);
    #undef LAYER_PASS

    // ---- final: 128 -> 2 dot + 0.5 (fp32); activations in A0 (plain halves) ----
    {
        int o = tid & 1, p = tid >> 1;
        float acc = smf[SMF_W4 + 256 + o];
        const __half2* arow = (const __half2*)(A0 + p * ASTR);
        const float* w4 = smf + SMF_W4 + o;
        #pragma unroll
        for (int j = 0; j < 64; j++) {
            float2 av = __half22float2(arow[j]);
            acc += av.x * w4[4 * j];
            acc += av.y * w4[4 * j + 2];
        }
        out[((size_t)b * NPIX + pbase + p) * 2 + o] = acc + 0.5f;
    }
}

// ---------------- launch ----------------
extern "C" void kernel_launch(void* const* d_in, const int* in_sizes, int n_in,
                              void* d_out, int out_size)
{
    const float* coord = (const float*)d_in[0];
    const float* lat   = (const float*)d_in[1];

    modulate_kernel<<<(2056 * 32 + 255) / 256, 256>>>(
        (const float*)d_in[2], (const float*)d_in[3], (const float*)d_in[4],
        (const float*)d_in[5], (const float*)d_in[6],
        (const float*)d_in[7], (const float*)d_in[8], (const float*)d_in[9],
        (const float*)d_in[10], (const float*)d_in[11]);

    cudaFuncSetAttribute(hyponet_kernel,
                         cudaFuncAttributeMaxDynamicSharedMemorySize, SMEM_BYTES);
    hyponet_kernel<<<BATCH * (NPIX / 64), 128, SMEM_BYTES>>>(coord, lat, (float*)d_out);
}